// round 7
// baseline (speedup 1.0000x reference)
#include <cuda_runtime.h>
#include <cstdint>

#define MDIM 1536
#define MM_ELEMS (1536 * 1536)

typedef unsigned long long ull;

// ---------------- scratch (static __device__, no allocation) ----------------
__device__ float g_TR[3ull * MM_ELEMS];   // T2, T3, T4 of Lr
__device__ float g_TC[3ull * MM_ELEMS];   // T2, T3, T4 of Lc
__device__ float g_Y [4ull * MM_ELEMS];   // Y1..Y4 = Tr_i @ x
__device__ float g_Z [20ull * MM_ELEMS];  // Z[i][j-1] = Y_i @ Tc_j

// ---------------- packed f32x2 helpers ----------------
__device__ __forceinline__ ull pack2(float lo, float hi) {
    ull r; asm("mov.b64 %0, {%1, %2};" : "=l"(r) : "f"(lo), "f"(hi)); return r;
}
__device__ __forceinline__ void fma2(ull& d, ull a, ull b) {
    asm("fma.rn.f32x2 %0, %1, %2, %0;" : "+l"(d) : "l"(a), "l"(b));
}
__device__ __forceinline__ float2 unpack2(ull v) {
    float2 f; asm("mov.b64 {%0, %1}, %2;" : "=f"(f.x), "=f"(f.y) : "l"(v)); return f;
}

// ---------------- batched square GEMM ----------------
// mode 0: C = A*B
// mode 1: C = 2*A*B - D   (D == nullptr -> D = Identity)
struct GemmArgs {
    const float* A[6];
    const float* B[6];
    const float* D[6];
    float*       C[6];
    int mode;
};

__global__ __launch_bounds__(256, 2)
void gemm_kernel(GemmArgs args) {
    const int bz = blockIdx.z;
    const float* __restrict__ A = args.A[bz];
    const float* __restrict__ B = args.B[bz];
    const float* Dm             = args.D[bz];
    float* __restrict__ C       = args.C[bz];

    __shared__ __align__(16) float As[16][128];   // As[k][m] (transposed)
    __shared__ __align__(16) float Bs[16][128];   // Bs[k][n]

    const int tid = threadIdx.x;
    const int tm  = tid >> 4;    // 0..15
    const int tn  = tid & 15;    // 0..15
    const int row0 = blockIdx.y * 128;
    const int col0 = blockIdx.x * 128;

    ull acc[8][4];
#pragma unroll
    for (int m = 0; m < 8; m++)
#pragma unroll
        for (int n = 0; n < 4; n++) acc[m][n] = 0ULL;

    for (int k0 = 0; k0 < MDIM; k0 += 16) {
        // load tiles (512 float4 each, 2 per thread)
#pragma unroll
        for (int it = 0; it < 2; it++) {
            int lin = tid + it * 256;
            // A tile: 128 rows x 16 k -> transposed scatter into As[k][m]
            int ar = lin >> 2;           // 0..127 (m)
            int ac = (lin & 3) << 2;     // 0,4,8,12 (k)
            float4 av = *(const float4*)(A + (size_t)(row0 + ar) * MDIM + k0 + ac);
            As[ac + 0][ar] = av.x;
            As[ac + 1][ar] = av.y;
            As[ac + 2][ar] = av.z;
            As[ac + 3][ar] = av.w;
            // B tile: 16 k-rows x 128 cols -> direct
            int br = lin >> 5;           // 0..15 (k)
            int bc = (lin & 31) << 2;    // 0..124 (n)
            *(float4*)&Bs[br][bc] = *(const float4*)(B + (size_t)(k0 + br) * MDIM + col0 + bc);
        }
        __syncthreads();

#pragma unroll
        for (int k = 0; k < 16; k++) {
            float4 a0 = *(const float4*)&As[k][tm * 8];
            float4 a1 = *(const float4*)&As[k][tm * 8 + 4];
            ulonglong2 bq0 = *(const ulonglong2*)&Bs[k][tn * 8];
            ulonglong2 bq1 = *(const ulonglong2*)&Bs[k][tn * 8 + 4];
            ull bv[4] = {bq0.x, bq0.y, bq1.x, bq1.y};
            float am[8] = {a0.x, a0.y, a0.z, a0.w, a1.x, a1.y, a1.z, a1.w};
#pragma unroll
            for (int m = 0; m < 8; m++) {
                ull aa = pack2(am[m], am[m]);
#pragma unroll
                for (int n = 0; n < 4; n++) fma2(acc[m][n], aa, bv[n]);
            }
        }
        __syncthreads();
    }

    // epilogue
    const int mode = args.mode;
#pragma unroll
    for (int m = 0; m < 8; m++) {
        int row = row0 + tm * 8 + m;
#pragma unroll
        for (int n = 0; n < 4; n++) {
            int col = col0 + tn * 8 + n * 2;
            float2 v = unpack2(acc[m][n]);
            if (mode) {
                float d0, d1;
                if (Dm) {
                    d0 = Dm[(size_t)row * MDIM + col];
                    d1 = Dm[(size_t)row * MDIM + col + 1];
                } else {
                    d0 = (row == col)     ? 1.0f : 0.0f;
                    d1 = (row == col + 1) ? 1.0f : 0.0f;
                }
                v.x = 2.0f * v.x - d0;
                v.y = 2.0f * v.y - d1;
            }
            *(float2*)(C + (size_t)row * MDIM + col) = v;
        }
    }
}

// ---------------- final contraction ----------------
// out[o,m,n] = bias[o] + sum_p theta[p,o] * Z_p[m,n]
// p = i*5 + j; Z_{i,0} = Y_i (Y_0 = x), Z_{i,j>=1} in g_Z[(i*4 + j-1)]
__global__ __launch_bounds__(256)
void final_kernel(const float* __restrict__ x,
                  const float* __restrict__ theta,
                  const float* __restrict__ bias,
                  float* __restrict__ out) {
    __shared__ float sth[25][32];
    __shared__ float sb[32];
    for (int t = threadIdx.x; t < 800; t += blockDim.x)
        sth[t >> 5][t & 31] = theta[t];
    if (threadIdx.x < 32) sb[threadIdx.x] = bias[threadIdx.x];
    __syncthreads();

    const int idx = blockIdx.x * blockDim.x + threadIdx.x;
    if (idx >= MM_ELEMS) return;

    float z[25];
    z[0] = x[idx];
#pragma unroll
    for (int i = 1; i < 5; i++)
        z[i * 5] = g_Y[(size_t)(i - 1) * MM_ELEMS + idx];
#pragma unroll
    for (int i = 0; i < 5; i++)
#pragma unroll
        for (int j = 1; j < 5; j++)
            z[i * 5 + j] = g_Z[(size_t)(i * 4 + j - 1) * MM_ELEMS + idx];

#pragma unroll 4
    for (int o = 0; o < 32; o++) {
        float acc = sb[o];
#pragma unroll
        for (int p = 0; p < 25; p++)
            acc = fmaf(z[p], sth[p][o], acc);
        out[(size_t)o * MM_ELEMS + idx] = acc;
    }
}

// ---------------- launch ----------------
extern "C" void kernel_launch(void* const* d_in, const int* in_sizes, int n_in,
                              void* d_out, int out_size) {
    const float* x  = (const float*)d_in[0];
    const float* Lr = (const float*)d_in[1];
    const float* Lc = (const float*)d_in[2];
    const float* th = (const float*)d_in[3];
    const float* bs = (const float*)d_in[4];
    float* out = (float*)d_out;

    float *tr, *tc, *y, *z;
    cudaGetSymbolAddress((void**)&tr, g_TR);
    cudaGetSymbolAddress((void**)&tc, g_TC);
    cudaGetSymbolAddress((void**)&y,  g_Y);
    cudaGetSymbolAddress((void**)&z,  g_Z);

    const dim3 blk(256);

    // --- Chebyshev recursion (row & col batched in z) ---
    {   // T2 = 2*L*L - I
        GemmArgs a = {};
        a.mode = 1;
        a.A[0] = Lr; a.B[0] = Lr; a.D[0] = nullptr; a.C[0] = tr;
        a.A[1] = Lc; a.B[1] = Lc; a.D[1] = nullptr; a.C[1] = tc;
        gemm_kernel<<<dim3(12, 12, 2), blk>>>(a);
    }
    {   // T3 = 2*L*T2 - L
        GemmArgs a = {};
        a.mode = 1;
        a.A[0] = Lr; a.B[0] = tr; a.D[0] = Lr; a.C[0] = tr + MM_ELEMS;
        a.A[1] = Lc; a.B[1] = tc; a.D[1] = Lc; a.C[1] = tc + MM_ELEMS;
        gemm_kernel<<<dim3(12, 12, 2), blk>>>(a);
    }
    {   // T4 = 2*L*T3 - T2
        GemmArgs a = {};
        a.mode = 1;
        a.A[0] = Lr; a.B[0] = tr + MM_ELEMS; a.D[0] = tr; a.C[0] = tr + 2 * (size_t)MM_ELEMS;
        a.A[1] = Lc; a.B[1] = tc + MM_ELEMS; a.D[1] = tc; a.C[1] = tc + 2 * (size_t)MM_ELEMS;
        gemm_kernel<<<dim3(12, 12, 2), blk>>>(a);
    }

    // --- Y_i = Tr_i @ x, i = 1..4 (batched z=4) ---
    {
        const float* trs[4] = {Lr, tr, tr + MM_ELEMS, tr + 2 * (size_t)MM_ELEMS};
        GemmArgs a = {};
        a.mode = 0;
        for (int i = 0; i < 4; i++) {
            a.A[i] = trs[i];
            a.B[i] = x;
            a.C[i] = y + (size_t)i * MM_ELEMS;
        }
        gemm_kernel<<<dim3(12, 12, 4), blk>>>(a);
    }

    // --- Z_{i,j} = Y_i @ Tc_j, i = 0..4 batched, one launch per j = 1..4 ---
    // FIX (R6): Tc_1 = Lc itself; scratch g_TC holds only {T2,T3,T4}.
    {
        const float* ys[5]  = {x, y, y + MM_ELEMS, y + 2 * (size_t)MM_ELEMS, y + 3 * (size_t)MM_ELEMS};
        const float* tcs[4] = {Lc, tc, tc + MM_ELEMS, tc + 2 * (size_t)MM_ELEMS};
        for (int j = 1; j <= 4; j++) {
            GemmArgs a = {};
            a.mode = 0;
            for (int i = 0; i < 5; i++) {
                a.A[i] = ys[i];
                a.B[i] = tcs[j - 1];
                a.C[i] = z + (size_t)(i * 4 + (j - 1)) * MM_ELEMS;
            }
            gemm_kernel<<<dim3(12, 12, 5), blk>>>(a);
        }
    }

    // --- final contraction ---
    final_kernel<<<MM_ELEMS / 256, blk>>>(x, th, bs, out);
}

// round 11
// speedup vs baseline: 2.5803x; 2.5803x over previous
#include <cuda_runtime.h>
#include <cuda_bf16.h>
#include <cstdint>

#define MDIM 1536
#define MM_ELEMS (1536 * 1536)
#define BM 128
#define BN 128
#define BK 64
#define NSTAGE (MDIM / BK)      // 24
#define TILE_BYTES 16384        // 128 rows x 64 bf16 x 2B
#define STAGE_BYTES (4 * TILE_BYTES)
#define GEMM_SMEM (2 * STAGE_BYTES)   // 131072

// ---------------- scratch (static __device__, no allocation) ----------------
__device__ float g_TR[3ull * MM_ELEMS];   // T2,T3,T4 of Lr (fp32)
__device__ float g_TC[3ull * MM_ELEMS];   // T2,T3,T4 of Lc (fp32)
__device__ float g_Y [4ull * MM_ELEMS];   // Y1..Y4 (fp32)
__device__ float g_Z [20ull * MM_ELEMS];  // Z (fp32)
// bf16 hi/lo slots: 0:Lr 1:Lc 2:x 3:xT 4..6:TR2..4 7..9:TC2..4 10..13:Y1..4
__device__ __nv_bfloat16 g_bh[14ull * MM_ELEMS];
__device__ __nv_bfloat16 g_bl[14ull * MM_ELEMS];

// ---------------- PTX helpers (all plain sm_80+ features) ----------------
__device__ __forceinline__ uint32_t smem_u32(const void* p) {
    uint32_t a;
    asm("{ .reg .u64 t; cvta.to.shared.u64 t, %1; cvt.u32.u64 %0, t; }" : "=r"(a) : "l"(p));
    return a;
}
__device__ __forceinline__ void cp16(uint32_t dst, const void* src) {
    asm volatile("cp.async.cg.shared.global [%0], [%1], 16;\n" :: "r"(dst), "l"(src));
}
__device__ __forceinline__ void cp_commit() {
    asm volatile("cp.async.commit_group;\n" ::: "memory");
}
template <int N>
__device__ __forceinline__ void cp_wait() {
    asm volatile("cp.async.wait_group %0;\n" :: "n"(N) : "memory");
}
__device__ __forceinline__ void ldsm4(uint32_t* r, uint32_t addr) {
    asm volatile("ldmatrix.sync.aligned.m8n8.x4.shared.b16 {%0,%1,%2,%3}, [%4];"
                 : "=r"(r[0]), "=r"(r[1]), "=r"(r[2]), "=r"(r[3]) : "r"(addr));
}
__device__ __forceinline__ void mma_bf16(float* c, const uint32_t* a, uint32_t b0, uint32_t b1) {
    asm volatile("mma.sync.aligned.m16n8k16.row.col.f32.bf16.bf16.f32 "
                 "{%0,%1,%2,%3}, {%4,%5,%6,%7}, {%8,%9}, {%0,%1,%2,%3};"
                 : "+f"(c[0]), "+f"(c[1]), "+f"(c[2]), "+f"(c[3])
                 : "r"(a[0]), "r"(a[1]), "r"(a[2]), "r"(a[3]), "r"(b0), "r"(b1));
}

// ---------------- batched split-bf16 GEMM (legacy tensor pipe) ----------------
// C = A*B (mode 0)  or  C = 2*A*B - D (mode 1, D==null -> Identity)
// A given row-major [m][k]; B given as [n][k] (i.e. B^T row-major; our B's are
// symmetric, or we pass an explicitly transposed slot). acc = AhBh+AhBl+AlBh.
struct GArgs {
    const __nv_bfloat16 *Ah[5], *Al[5], *Bh[5], *Bl[5];
    const float* D[5];
    float* C[5];
    __nv_bfloat16 *Ch[5], *Cl[5];
    int mode;
};

__global__ __launch_bounds__(256, 1)
void gemm_mma(GArgs args) {
    extern __shared__ char smem[];
    const int bz = blockIdx.z;
    const __nv_bfloat16* __restrict__ Ah = args.Ah[bz];
    const __nv_bfloat16* __restrict__ Al = args.Al[bz];
    const __nv_bfloat16* __restrict__ Bh = args.Bh[bz];
    const __nv_bfloat16* __restrict__ Bl = args.Bl[bz];
    const float* Dm = args.D[bz];
    float*       C  = args.C[bz];
    __nv_bfloat16* Ch = args.Ch[bz];
    __nv_bfloat16* Cl = args.Cl[bz];

    const uint32_t sb = smem_u32(smem);
    const int tid = threadIdx.x;
    const int wid = tid >> 5;
    const int l   = tid & 31;
    const int wm  = wid & 3;      // 4 warps along M (32 rows each)
    const int wn  = wid >> 2;     // 2 warps along N (64 cols each)
    const int row0 = blockIdx.y * BM;
    const int col0 = blockIdx.x * BN;

    float acc[2][8][4];
#pragma unroll
    for (int mf = 0; mf < 2; mf++)
#pragma unroll
        for (int nf = 0; nf < 8; nf++)
#pragma unroll
            for (int q = 0; q < 4; q++) acc[mf][nf][q] = 0.0f;

    const __nv_bfloat16* P[4] = {Ah, Al, Bh, Bl};

    // ---- stage loader: 16 cp.async(16B) per thread ----
    auto load_stage = [&](int s, int buf) {
        const int kb = s * BK;
        const uint32_t base = sb + buf * STAGE_BYTES;
#pragma unroll
        for (int t = 0; t < 4; t++) {
            const __nv_bfloat16* p = P[t];
            const int rb = (t < 2) ? row0 : col0;
#pragma unroll
            for (int i = 0; i < 4; i++) {
                int idx = tid + 256 * i;
                int r = idx >> 3, c16 = idx & 7;
                uint32_t dst = base + t * TILE_BYTES + r * 128 + ((c16 ^ (r & 7)) << 4);
                cp16(dst, p + (size_t)(rb + r) * MDIM + kb + c16 * 8);
            }
        }
        cp_commit();
    };

    // ---- compute one resident stage: 4 k16-steps, 3 product passes ----
    auto compute = [&](int buf) {
        const uint32_t base = sb + buf * STAGE_BYTES;
#pragma unroll
        for (int ks = 0; ks < 4; ks++) {
            uint32_t aH[2][4], aL[2][4], bH[4][4], bL[4][4];
            const int c16 = ks * 2 + (l >> 4);
#pragma unroll
            for (int mf = 0; mf < 2; mf++) {
                int ar = wm * 32 + mf * 16 + (l & 15);
                uint32_t off = (uint32_t)(ar * 128 + ((c16 ^ (ar & 7)) << 4));
                ldsm4(aH[mf], base + off);
                ldsm4(aL[mf], base + TILE_BYTES + off);
            }
#pragma unroll
            for (int np = 0; np < 4; np++) {
                int br = wn * 64 + np * 16 + (l & 15);
                uint32_t off = (uint32_t)(br * 128 + ((c16 ^ (br & 7)) << 4));
                ldsm4(bH[np], base + 2 * TILE_BYTES + off);
                ldsm4(bL[np], base + 3 * TILE_BYTES + off);
            }
#pragma unroll
            for (int mf = 0; mf < 2; mf++)
#pragma unroll
                for (int nf = 0; nf < 8; nf++) {
                    const int np = nf >> 1, s2 = nf & 1;
                    mma_bf16(acc[mf][nf], aH[mf], bH[np][s2], bH[np][s2 + 2]);
                    mma_bf16(acc[mf][nf], aH[mf], bL[np][s2], bL[np][s2 + 2]);
                    mma_bf16(acc[mf][nf], aL[mf], bH[np][s2], bH[np][s2 + 2]);
                }
        }
    };

    // ---- main loop: double-buffered ----
    load_stage(0, 0);
    for (int s = 0; s < NSTAGE; s++) {
        if (s + 1 < NSTAGE) { load_stage(s + 1, (s + 1) & 1); cp_wait<1>(); }
        else                { cp_wait<0>(); }
        __syncthreads();
        compute(s & 1);
        __syncthreads();
    }

    // ---- epilogue ----
    const int mode = args.mode;
#pragma unroll
    for (int mf = 0; mf < 2; mf++) {
#pragma unroll
        for (int nf = 0; nf < 8; nf++) {
            const int r0 = row0 + wm * 32 + mf * 16 + (l >> 2);
            const int r1 = r0 + 8;
            const int cc = col0 + wn * 64 + nf * 8 + (l & 3) * 2;
            float v0 = acc[mf][nf][0], v1 = acc[mf][nf][1];
            float v2 = acc[mf][nf][2], v3 = acc[mf][nf][3];
            if (mode) {
                float d0, d1, d2, d3;
                if (Dm) {
                    d0 = Dm[(size_t)r0 * MDIM + cc];
                    d1 = Dm[(size_t)r0 * MDIM + cc + 1];
                    d2 = Dm[(size_t)r1 * MDIM + cc];
                    d3 = Dm[(size_t)r1 * MDIM + cc + 1];
                } else {
                    d0 = (r0 == cc) ? 1.0f : 0.0f;
                    d1 = (r0 == cc + 1) ? 1.0f : 0.0f;
                    d2 = (r1 == cc) ? 1.0f : 0.0f;
                    d3 = (r1 == cc + 1) ? 1.0f : 0.0f;
                }
                v0 = 2.0f * v0 - d0; v1 = 2.0f * v1 - d1;
                v2 = 2.0f * v2 - d2; v3 = 2.0f * v3 - d3;
            }
            *(float2*)&C[(size_t)r0 * MDIM + cc] = make_float2(v0, v1);
            *(float2*)&C[(size_t)r1 * MDIM + cc] = make_float2(v2, v3);
            if (Ch) {
                __nv_bfloat16 h0 = __float2bfloat16_rn(v0), h1 = __float2bfloat16_rn(v1);
                __nv_bfloat16 h2 = __float2bfloat16_rn(v2), h3 = __float2bfloat16_rn(v3);
                __nv_bfloat162 hp0 = __halves2bfloat162(h0, h1);
                __nv_bfloat162 hp1 = __halves2bfloat162(h2, h3);
                __nv_bfloat162 lp0 = __halves2bfloat162(
                    __float2bfloat16_rn(v0 - __bfloat162float(h0)),
                    __float2bfloat16_rn(v1 - __bfloat162float(h1)));
                __nv_bfloat162 lp1 = __halves2bfloat162(
                    __float2bfloat16_rn(v2 - __bfloat162float(h2)),
                    __float2bfloat16_rn(v3 - __bfloat162float(h3)));
                *(__nv_bfloat162*)&Ch[(size_t)r0 * MDIM + cc] = hp0;
                *(__nv_bfloat162*)&Ch[(size_t)r1 * MDIM + cc] = hp1;
                *(__nv_bfloat162*)&Cl[(size_t)r0 * MDIM + cc] = lp0;
                *(__nv_bfloat162*)&Cl[(size_t)r1 * MDIM + cc] = lp1;
            }
        }
    }
}

// ---------------- fp32 -> bf16 hi/lo converters ----------------
__global__ __launch_bounds__(256)
void conv_kernel(const float* __restrict__ s, __nv_bfloat16* __restrict__ h,
                 __nv_bfloat16* __restrict__ l) {
    int i = blockIdx.x * 256 + threadIdx.x;   // 4 elems per thread
    float4 v = ((const float4*)s)[i];
    float vv[4] = {v.x, v.y, v.z, v.w};
    uint32_t hw[2], lw[2];
#pragma unroll
    for (int q = 0; q < 2; q++) {
        __nv_bfloat16 h0 = __float2bfloat16_rn(vv[2 * q]);
        __nv_bfloat16 h1 = __float2bfloat16_rn(vv[2 * q + 1]);
        __nv_bfloat16 l0 = __float2bfloat16_rn(vv[2 * q]     - __bfloat162float(h0));
        __nv_bfloat16 l1 = __float2bfloat16_rn(vv[2 * q + 1] - __bfloat162float(h1));
        __nv_bfloat162 hp = __halves2bfloat162(h0, h1);
        __nv_bfloat162 lp = __halves2bfloat162(l0, l1);
        hw[q] = *(uint32_t*)&hp;
        lw[q] = *(uint32_t*)&lp;
    }
    ((uint2*)h)[i] = make_uint2(hw[0], hw[1]);
    ((uint2*)l)[i] = make_uint2(lw[0], lw[1]);
}

__global__ __launch_bounds__(256)
void convT_kernel(const float* __restrict__ s, __nv_bfloat16* __restrict__ h,
                  __nv_bfloat16* __restrict__ l) {
    __shared__ float t[32][33];
    const int bx = blockIdx.x * 32, by = blockIdx.y * 32;
    const int x = threadIdx.x, y = threadIdx.y;   // 32 x 8
#pragma unroll
    for (int j = 0; j < 4; j++)
        t[y + 8 * j][x] = s[(size_t)(by + y + 8 * j) * MDIM + bx + x];
    __syncthreads();
#pragma unroll
    for (int j = 0; j < 4; j++) {
        float v = t[x][y + 8 * j];
        __nv_bfloat16 hv = __float2bfloat16_rn(v);
        __nv_bfloat16 lv = __float2bfloat16_rn(v - __bfloat162float(hv));
        size_t o = (size_t)(bx + y + 8 * j) * MDIM + by + x;
        h[o] = hv; l[o] = lv;
    }
}

// ---------------- final contraction ----------------
__global__ __launch_bounds__(256)
void final_kernel(const float* __restrict__ x,
                  const float* __restrict__ theta,
                  const float* __restrict__ bias,
                  float* __restrict__ out) {
    __shared__ float sth[25][32];
    __shared__ float sb[32];
    for (int t = threadIdx.x; t < 800; t += blockDim.x)
        sth[t >> 5][t & 31] = theta[t];
    if (threadIdx.x < 32) sb[threadIdx.x] = bias[threadIdx.x];
    __syncthreads();

    const int idx = blockIdx.x * blockDim.x + threadIdx.x;
    float z[25];
    z[0] = x[idx];
#pragma unroll
    for (int i = 1; i < 5; i++)
        z[i * 5] = g_Y[(size_t)(i - 1) * MM_ELEMS + idx];
#pragma unroll
    for (int i = 0; i < 5; i++)
#pragma unroll
        for (int j = 1; j < 5; j++)
            z[i * 5 + j] = g_Z[(size_t)(i * 4 + j - 1) * MM_ELEMS + idx];

#pragma unroll 4
    for (int o = 0; o < 32; o++) {
        float acc = sb[o];
#pragma unroll
        for (int p = 0; p < 25; p++)
            acc = fmaf(z[p], sth[p][o], acc);
        out[(size_t)o * MM_ELEMS + idx] = acc;
    }
}

// ---------------- launch ----------------
extern "C" void kernel_launch(void* const* d_in, const int* in_sizes, int n_in,
                              void* d_out, int out_size) {
    const float* x  = (const float*)d_in[0];
    const float* Lr = (const float*)d_in[1];
    const float* Lc = (const float*)d_in[2];
    const float* th = (const float*)d_in[3];
    const float* bs = (const float*)d_in[4];
    float* out = (float*)d_out;

    cudaFuncSetAttribute(gemm_mma, cudaFuncAttributeMaxDynamicSharedMemorySize, GEMM_SMEM);

    float *tr, *tc, *y, *z;
    __nv_bfloat16 *bh, *bl;
    cudaGetSymbolAddress((void**)&tr, g_TR);
    cudaGetSymbolAddress((void**)&tc, g_TC);
    cudaGetSymbolAddress((void**)&y,  g_Y);
    cudaGetSymbolAddress((void**)&z,  g_Z);
    cudaGetSymbolAddress((void**)&bh, g_bh);
    cudaGetSymbolAddress((void**)&bl, g_bl);

    auto H = [&](int s) { return bh + (size_t)s * MM_ELEMS; };
    auto L = [&](int s) { return bl + (size_t)s * MM_ELEMS; };

    // --- converts: Lr->0, Lc->1, x->2, xT->3 ---
    conv_kernel<<<MM_ELEMS / 1024, 256>>>(Lr, H(0), L(0));
    conv_kernel<<<MM_ELEMS / 1024, 256>>>(Lc, H(1), L(1));
    conv_kernel<<<MM_ELEMS / 1024, 256>>>(x,  H(2), L(2));
    convT_kernel<<<dim3(48, 48), dim3(32, 8)>>>(x, H(3), L(3));

    const dim3 gblk(256);

    // --- Chebyshev recursion, row & col batched (z=2) ---
    {   // T2 = 2*L*L - I  -> slots 4 (row), 7 (col)
        GArgs a = {}; a.mode = 1;
        a.Ah[0]=H(0); a.Al[0]=L(0); a.Bh[0]=H(0); a.Bl[0]=L(0); a.D[0]=nullptr;
        a.C[0]=tr; a.Ch[0]=H(4); a.Cl[0]=L(4);
        a.Ah[1]=H(1); a.Al[1]=L(1); a.Bh[1]=H(1); a.Bl[1]=L(1); a.D[1]=nullptr;
        a.C[1]=tc; a.Ch[1]=H(7); a.Cl[1]=L(7);
        gemm_mma<<<dim3(12, 12, 2), gblk, GEMM_SMEM>>>(a);
    }
    {   // T3 = 2*L*T2 - L  -> slots 5, 8
        GArgs a = {}; a.mode = 1;
        a.Ah[0]=H(0); a.Al[0]=L(0); a.Bh[0]=H(4); a.Bl[0]=L(4); a.D[0]=Lr;
        a.C[0]=tr + MM_ELEMS; a.Ch[0]=H(5); a.Cl[0]=L(5);
        a.Ah[1]=H(1); a.Al[1]=L(1); a.Bh[1]=H(7); a.Bl[1]=L(7); a.D[1]=Lc;
        a.C[1]=tc + MM_ELEMS; a.Ch[1]=H(8); a.Cl[1]=L(8);
        gemm_mma<<<dim3(12, 12, 2), gblk, GEMM_SMEM>>>(a);
    }
    {   // T4 = 2*L*T3 - T2 -> slots 6, 9
        GArgs a = {}; a.mode = 1;
        a.Ah[0]=H(0); a.Al[0]=L(0); a.Bh[0]=H(5); a.Bl[0]=L(5); a.D[0]=tr;
        a.C[0]=tr + 2 * (size_t)MM_ELEMS; a.Ch[0]=H(6); a.Cl[0]=L(6);
        a.Ah[1]=H(1); a.Al[1]=L(1); a.Bh[1]=H(8); a.Bl[1]=L(8); a.D[1]=tc;
        a.C[1]=tc + 2 * (size_t)MM_ELEMS; a.Ch[1]=H(9); a.Cl[1]=L(9);
        gemm_mma<<<dim3(12, 12, 2), gblk, GEMM_SMEM>>>(a);
    }

    // --- Y_i = Tr_i @ x (B operand = xT slot), i=1..4 (z=4) ---
    {
        const int trs[4] = {0, 4, 5, 6};
        GArgs a = {}; a.mode = 0;
        for (int i = 0; i < 4; i++) {
            a.Ah[i] = H(trs[i]); a.Al[i] = L(trs[i]);
            a.Bh[i] = H(3);      a.Bl[i] = L(3);
            a.D[i]  = nullptr;
            a.C[i]  = y + (size_t)i * MM_ELEMS;
            a.Ch[i] = H(10 + i); a.Cl[i] = L(10 + i);
        }
        gemm_mma<<<dim3(12, 12, 4), gblk, GEMM_SMEM>>>(a);
    }

    // --- Z_{i,j} = Y_i @ Tc_j (Tc symmetric -> B needs no transpose), z=5 per j ---
    {
        const int ysl[5] = {2, 10, 11, 12, 13};      // x, Y1..Y4
        const int tcs[4] = {1, 7, 8, 9};             // Lc, T2c, T3c, T4c
        for (int j = 1; j <= 4; j++) {
            GArgs a = {}; a.mode = 0;
            for (int i = 0; i < 5; i++) {
                a.Ah[i] = H(ysl[i]); a.Al[i] = L(ysl[i]);
                a.Bh[i] = H(tcs[j - 1]); a.Bl[i] = L(tcs[j - 1]);
                a.D[i] = nullptr;
                a.C[i] = z + (size_t)(i * 4 + (j - 1)) * MM_ELEMS;
                a.Ch[i] = nullptr; a.Cl[i] = nullptr;
            }
            gemm_mma<<<dim3(12, 12, 5), gblk, GEMM_SMEM>>>(a);
        }
    }

    // --- final contraction ---
    final_kernel<<<MM_ELEMS / 256, gblk>>>(x, th, bs, out);
}

// round 12
// speedup vs baseline: 2.6575x; 1.0299x over previous
#include <cuda_runtime.h>
#include <cuda_bf16.h>
#include <cstdint>

#define MDIM 1536
#define MM_ELEMS (1536 * 1536)
#define BM 128
#define BN 128
#define BK 64
#define NSTAGE (MDIM / BK)      // 24
#define TILE_BYTES 16384        // 128 rows x 64 bf16 x 2B
#define STAGE_BYTES (4 * TILE_BYTES)          // 64KB
#define GEMM_SMEM (3 * STAGE_BYTES)           // 196608 (3-stage)

// ---------------- scratch (static __device__, no allocation) ----------------
__device__ float g_TR[3ull * MM_ELEMS];   // T2,T3,T4 of Lr (fp32)
__device__ float g_TC[3ull * MM_ELEMS];   // T2,T3,T4 of Lc (fp32)
__device__ float g_Y [4ull * MM_ELEMS];   // Y1..Y4 (fp32)
__device__ float g_Z [20ull * MM_ELEMS];  // Z (fp32)
// bf16 hi/lo slots: 0:Lr 1:Lc 2:x 3:xT 4..6:TR2..4 7..9:TC2..4 10..13:Y1..4
__device__ __nv_bfloat16 g_bh[14ull * MM_ELEMS];
__device__ __nv_bfloat16 g_bl[14ull * MM_ELEMS];

// ---------------- PTX helpers (plain sm_80+ features only) ----------------
__device__ __forceinline__ uint32_t smem_u32(const void* p) {
    uint32_t a;
    asm("{ .reg .u64 t; cvta.to.shared.u64 t, %1; cvt.u32.u64 %0, t; }" : "=r"(a) : "l"(p));
    return a;
}
__device__ __forceinline__ void cp16(uint32_t dst, const void* src) {
    asm volatile("cp.async.cg.shared.global [%0], [%1], 16;\n" :: "r"(dst), "l"(src));
}
__device__ __forceinline__ void cp_commit() {
    asm volatile("cp.async.commit_group;\n" ::: "memory");
}
template <int N>
__device__ __forceinline__ void cp_wait() {
    asm volatile("cp.async.wait_group %0;\n" :: "n"(N) : "memory");
}
__device__ __forceinline__ void ldsm4(uint32_t* r, uint32_t addr) {
    asm volatile("ldmatrix.sync.aligned.m8n8.x4.shared.b16 {%0,%1,%2,%3}, [%4];"
                 : "=r"(r[0]), "=r"(r[1]), "=r"(r[2]), "=r"(r[3]) : "r"(addr));
}
__device__ __forceinline__ void mma_bf16(float* c, const uint32_t* a, uint32_t b0, uint32_t b1) {
    asm volatile("mma.sync.aligned.m16n8k16.row.col.f32.bf16.bf16.f32 "
                 "{%0,%1,%2,%3}, {%4,%5,%6,%7}, {%8,%9}, {%0,%1,%2,%3};"
                 : "+f"(c[0]), "+f"(c[1]), "+f"(c[2]), "+f"(c[3])
                 : "r"(a[0]), "r"(a[1]), "r"(a[2]), "r"(a[3]), "r"(b0), "r"(b1));
}

// ---------------- batched split-bf16 GEMM (legacy tensor pipe) ----------------
// C = A*B (mode 0)  or  C = 2*A*B - D (mode 1, D==null -> Identity)
// A row-major [m][k]; B as [n][k] (B^T row-major; symmetric B's or explicit xT).
// acc = AhBh + AhBl + AlBh.
#define MAXB 20
struct GArgs {
    const __nv_bfloat16 *Ah[MAXB], *Al[MAXB], *Bh[MAXB], *Bl[MAXB];
    const float* D[MAXB];
    float* C[MAXB];
    __nv_bfloat16 *Ch[MAXB], *Cl[MAXB];
    int mode;
};

__global__ __launch_bounds__(256, 1)
void gemm_mma(GArgs args) {
    extern __shared__ char smem[];
    const int bz = blockIdx.z;
    const __nv_bfloat16* __restrict__ Ah = args.Ah[bz];
    const __nv_bfloat16* __restrict__ Al = args.Al[bz];
    const __nv_bfloat16* __restrict__ Bh = args.Bh[bz];
    const __nv_bfloat16* __restrict__ Bl = args.Bl[bz];
    const float* Dm = args.D[bz];
    float*       C  = args.C[bz];
    __nv_bfloat16* Ch = args.Ch[bz];
    __nv_bfloat16* Cl = args.Cl[bz];

    const uint32_t sb = smem_u32(smem);
    const int tid = threadIdx.x;
    const int wid = tid >> 5;
    const int l   = tid & 31;
    const int wm  = wid & 3;      // 4 warps along M (32 rows each)
    const int wn  = wid >> 2;     // 2 warps along N (64 cols each)
    const int row0 = blockIdx.y * BM;
    const int col0 = blockIdx.x * BN;

    float acc[2][8][4];
#pragma unroll
    for (int mf = 0; mf < 2; mf++)
#pragma unroll
        for (int nf = 0; nf < 8; nf++)
#pragma unroll
            for (int q = 0; q < 4; q++) acc[mf][nf][q] = 0.0f;

    const __nv_bfloat16* P[4] = {Ah, Al, Bh, Bl};

    // ---- stage loader: 16 cp.async(16B) per thread, one commit group ----
    auto load_stage = [&](int s, int buf) {
        const int kb = s * BK;
        const uint32_t base = sb + buf * STAGE_BYTES;
#pragma unroll
        for (int t = 0; t < 4; t++) {
            const __nv_bfloat16* p = P[t];
            const int rb = (t < 2) ? row0 : col0;
#pragma unroll
            for (int i = 0; i < 4; i++) {
                int idx = tid + 256 * i;
                int r = idx >> 3, c16 = idx & 7;
                uint32_t dst = base + t * TILE_BYTES + r * 128 + ((c16 ^ (r & 7)) << 4);
                cp16(dst, p + (size_t)(rb + r) * MDIM + kb + c16 * 8);
            }
        }
        cp_commit();
    };

    // ---- compute one resident stage: 4 k16-steps x 3 product passes ----
    auto compute = [&](int buf) {
        const uint32_t base = sb + buf * STAGE_BYTES;
#pragma unroll
        for (int ks = 0; ks < 4; ks++) {
            uint32_t aH[2][4], aL[2][4], bH[4][4], bL[4][4];
            const int c16 = ks * 2 + (l >> 4);
#pragma unroll
            for (int mf = 0; mf < 2; mf++) {
                int ar = wm * 32 + mf * 16 + (l & 15);
                uint32_t off = (uint32_t)(ar * 128 + ((c16 ^ (ar & 7)) << 4));
                ldsm4(aH[mf], base + off);
                ldsm4(aL[mf], base + TILE_BYTES + off);
            }
#pragma unroll
            for (int np = 0; np < 4; np++) {
                int br = wn * 64 + np * 16 + (l & 15);
                uint32_t off = (uint32_t)(br * 128 + ((c16 ^ (br & 7)) << 4));
                ldsm4(bH[np], base + 2 * TILE_BYTES + off);
                ldsm4(bL[np], base + 3 * TILE_BYTES + off);
            }
#pragma unroll
            for (int mf = 0; mf < 2; mf++)
#pragma unroll
                for (int nf = 0; nf < 8; nf++) {
                    const int np = nf >> 1, s2 = nf & 1;
                    mma_bf16(acc[mf][nf], aH[mf], bH[np][s2], bH[np][s2 + 2]);
                    mma_bf16(acc[mf][nf], aH[mf], bL[np][s2], bL[np][s2 + 2]);
                    mma_bf16(acc[mf][nf], aL[mf], bH[np][s2], bH[np][s2 + 2]);
                }
        }
    };

    // ---- 3-stage pipeline, ONE barrier per stage ----
    // iter s: sync; issue load(s+2); wait<=2 pending (=> stage s resident); compute(s)
    // safety: load(s+2) writes buf (s+2)%3 == (s-1)%3, whose compute finished
    // before this iteration's barrier.
    load_stage(0, 0);
    load_stage(1, 1);
    for (int s = 0; s < NSTAGE; s++) {
        __syncthreads();
        if (s + 2 < NSTAGE) { load_stage(s + 2, (s + 2) % 3); cp_wait<2>(); }
        else if (s + 1 < NSTAGE) { cp_wait<1>(); }
        else { cp_wait<0>(); }
        __syncthreads();   // all threads see stage s data before any reads
        compute(s % 3);
    }

    // ---- epilogue ----
    const int mode = args.mode;
#pragma unroll
    for (int mf = 0; mf < 2; mf++) {
#pragma unroll
        for (int nf = 0; nf < 8; nf++) {
            const int r0 = row0 + wm * 32 + mf * 16 + (l >> 2);
            const int r1 = r0 + 8;
            const int cc = col0 + wn * 64 + nf * 8 + (l & 3) * 2;
            float v0 = acc[mf][nf][0], v1 = acc[mf][nf][1];
            float v2 = acc[mf][nf][2], v3 = acc[mf][nf][3];
            if (mode) {
                float d0, d1, d2, d3;
                if (Dm) {
                    d0 = Dm[(size_t)r0 * MDIM + cc];
                    d1 = Dm[(size_t)r0 * MDIM + cc + 1];
                    d2 = Dm[(size_t)r1 * MDIM + cc];
                    d3 = Dm[(size_t)r1 * MDIM + cc + 1];
                } else {
                    d0 = (r0 == cc) ? 1.0f : 0.0f;
                    d1 = (r0 == cc + 1) ? 1.0f : 0.0f;
                    d2 = (r1 == cc) ? 1.0f : 0.0f;
                    d3 = (r1 == cc + 1) ? 1.0f : 0.0f;
                }
                v0 = 2.0f * v0 - d0; v1 = 2.0f * v1 - d1;
                v2 = 2.0f * v2 - d2; v3 = 2.0f * v3 - d3;
            }
            *(float2*)&C[(size_t)r0 * MDIM + cc] = make_float2(v0, v1);
            *(float2*)&C[(size_t)r1 * MDIM + cc] = make_float2(v2, v3);
            if (Ch) {
                __nv_bfloat16 h0 = __float2bfloat16_rn(v0), h1 = __float2bfloat16_rn(v1);
                __nv_bfloat16 h2 = __float2bfloat16_rn(v2), h3 = __float2bfloat16_rn(v3);
                __nv_bfloat162 hp0 = __halves2bfloat162(h0, h1);
                __nv_bfloat162 hp1 = __halves2bfloat162(h2, h3);
                __nv_bfloat162 lp0 = __halves2bfloat162(
                    __float2bfloat16_rn(v0 - __bfloat162float(h0)),
                    __float2bfloat16_rn(v1 - __bfloat162float(h1)));
                __nv_bfloat162 lp1 = __halves2bfloat162(
                    __float2bfloat16_rn(v2 - __bfloat162float(h2)),
                    __float2bfloat16_rn(v3 - __bfloat162float(h3)));
                *(__nv_bfloat162*)&Ch[(size_t)r0 * MDIM + cc] = hp0;
                *(__nv_bfloat162*)&Ch[(size_t)r1 * MDIM + cc] = hp1;
                *(__nv_bfloat162*)&Cl[(size_t)r0 * MDIM + cc] = lp0;
                *(__nv_bfloat162*)&Cl[(size_t)r1 * MDIM + cc] = lp1;
            }
        }
    }
}

// ---------------- fp32 -> bf16 hi/lo converters ----------------
__global__ __launch_bounds__(256)
void conv_kernel(const float* __restrict__ s, __nv_bfloat16* __restrict__ h,
                 __nv_bfloat16* __restrict__ l) {
    int i = blockIdx.x * 256 + threadIdx.x;   // 4 elems per thread
    float4 v = ((const float4*)s)[i];
    float vv[4] = {v.x, v.y, v.z, v.w};
    uint32_t hw[2], lw[2];
#pragma unroll
    for (int q = 0; q < 2; q++) {
        __nv_bfloat16 h0 = __float2bfloat16_rn(vv[2 * q]);
        __nv_bfloat16 h1 = __float2bfloat16_rn(vv[2 * q + 1]);
        __nv_bfloat16 l0 = __float2bfloat16_rn(vv[2 * q]     - __bfloat162float(h0));
        __nv_bfloat16 l1 = __float2bfloat16_rn(vv[2 * q + 1] - __bfloat162float(h1));
        __nv_bfloat162 hp = __halves2bfloat162(h0, h1);
        __nv_bfloat162 lp = __halves2bfloat162(l0, l1);
        hw[q] = *(uint32_t*)&hp;
        lw[q] = *(uint32_t*)&lp;
    }
    ((uint2*)h)[i] = make_uint2(hw[0], hw[1]);
    ((uint2*)l)[i] = make_uint2(lw[0], lw[1]);
}

__global__ __launch_bounds__(256)
void convT_kernel(const float* __restrict__ s, __nv_bfloat16* __restrict__ h,
                  __nv_bfloat16* __restrict__ l) {
    __shared__ float t[32][33];
    const int bx = blockIdx.x * 32, by = blockIdx.y * 32;
    const int x = threadIdx.x, y = threadIdx.y;   // 32 x 8
#pragma unroll
    for (int j = 0; j < 4; j++)
        t[y + 8 * j][x] = s[(size_t)(by + y + 8 * j) * MDIM + bx + x];
    __syncthreads();
#pragma unroll
    for (int j = 0; j < 4; j++) {
        float v = t[x][y + 8 * j];
        __nv_bfloat16 hv = __float2bfloat16_rn(v);
        __nv_bfloat16 lv = __float2bfloat16_rn(v - __bfloat162float(hv));
        size_t o = (size_t)(bx + y + 8 * j) * MDIM + by + x;
        h[o] = hv; l[o] = lv;
    }
}

// ---------------- final contraction (float4 vectorized) ----------------
__global__ __launch_bounds__(256)
void final_kernel(const float* __restrict__ x,
                  const float* __restrict__ theta,
                  const float* __restrict__ bias,
                  float* __restrict__ out) {
    __shared__ float sth[25][32];
    __shared__ float sb[32];
    for (int t = threadIdx.x; t < 800; t += blockDim.x)
        sth[t >> 5][t & 31] = theta[t];
    if (threadIdx.x < 32) sb[threadIdx.x] = bias[threadIdx.x];
    __syncthreads();

    const size_t i4 = (size_t)blockIdx.x * blockDim.x + threadIdx.x;  // float4 index
    float4 z[25];
    z[0] = ((const float4*)x)[i4];
#pragma unroll
    for (int i = 1; i < 5; i++)
        z[i * 5] = ((const float4*)g_Y)[(size_t)(i - 1) * (MM_ELEMS / 4) + i4];
#pragma unroll
    for (int i = 0; i < 5; i++)
#pragma unroll
        for (int j = 1; j < 5; j++)
            z[i * 5 + j] = ((const float4*)g_Z)[(size_t)(i * 4 + j - 1) * (MM_ELEMS / 4) + i4];

#pragma unroll 4
    for (int o = 0; o < 32; o++) {
        float b = sb[o];
        float4 a = make_float4(b, b, b, b);
#pragma unroll
        for (int p = 0; p < 25; p++) {
            float w = sth[p][o];
            a.x = fmaf(z[p].x, w, a.x);
            a.y = fmaf(z[p].y, w, a.y);
            a.z = fmaf(z[p].z, w, a.z);
            a.w = fmaf(z[p].w, w, a.w);
        }
        ((float4*)out)[(size_t)o * (MM_ELEMS / 4) + i4] = a;
    }
}

// ---------------- launch ----------------
extern "C" void kernel_launch(void* const* d_in, const int* in_sizes, int n_in,
                              void* d_out, int out_size) {
    const float* x  = (const float*)d_in[0];
    const float* Lr = (const float*)d_in[1];
    const float* Lc = (const float*)d_in[2];
    const float* th = (const float*)d_in[3];
    const float* bs = (const float*)d_in[4];
    float* out = (float*)d_out;

    cudaFuncSetAttribute(gemm_mma, cudaFuncAttributeMaxDynamicSharedMemorySize, GEMM_SMEM);

    float *tr, *tc, *y, *z;
    __nv_bfloat16 *bh, *bl;
    cudaGetSymbolAddress((void**)&tr, g_TR);
    cudaGetSymbolAddress((void**)&tc, g_TC);
    cudaGetSymbolAddress((void**)&y,  g_Y);
    cudaGetSymbolAddress((void**)&z,  g_Z);
    cudaGetSymbolAddress((void**)&bh, g_bh);
    cudaGetSymbolAddress((void**)&bl, g_bl);

    auto H = [&](int s) { return bh + (size_t)s * MM_ELEMS; };
    auto L = [&](int s) { return bl + (size_t)s * MM_ELEMS; };

    // --- converts: Lr->0, Lc->1, x->2, xT->3 ---
    conv_kernel<<<MM_ELEMS / 1024, 256>>>(Lr, H(0), L(0));
    conv_kernel<<<MM_ELEMS / 1024, 256>>>(Lc, H(1), L(1));
    conv_kernel<<<MM_ELEMS / 1024, 256>>>(x,  H(2), L(2));
    convT_kernel<<<dim3(48, 48), dim3(32, 8)>>>(x, H(3), L(3));

    const dim3 gblk(256);

    // --- Chebyshev recursion, row & col batched (z=2) ---
    {   // T2 = 2*L*L - I  -> slots 4 (row), 7 (col)
        GArgs a = {}; a.mode = 1;
        a.Ah[0]=H(0); a.Al[0]=L(0); a.Bh[0]=H(0); a.Bl[0]=L(0); a.D[0]=nullptr;
        a.C[0]=tr; a.Ch[0]=H(4); a.Cl[0]=L(4);
        a.Ah[1]=H(1); a.Al[1]=L(1); a.Bh[1]=H(1); a.Bl[1]=L(1); a.D[1]=nullptr;
        a.C[1]=tc; a.Ch[1]=H(7); a.Cl[1]=L(7);
        gemm_mma<<<dim3(12, 12, 2), gblk, GEMM_SMEM>>>(a);
    }
    {   // T3 = 2*L*T2 - L  -> slots 5, 8
        GArgs a = {}; a.mode = 1;
        a.Ah[0]=H(0); a.Al[0]=L(0); a.Bh[0]=H(4); a.Bl[0]=L(4); a.D[0]=Lr;
        a.C[0]=tr + MM_ELEMS; a.Ch[0]=H(5); a.Cl[0]=L(5);
        a.Ah[1]=H(1); a.Al[1]=L(1); a.Bh[1]=H(7); a.Bl[1]=L(7); a.D[1]=Lc;
        a.C[1]=tc + MM_ELEMS; a.Ch[1]=H(8); a.Cl[1]=L(8);
        gemm_mma<<<dim3(12, 12, 2), gblk, GEMM_SMEM>>>(a);
    }
    {   // T4 = 2*L*T3 - T2 -> slots 6, 9
        GArgs a = {}; a.mode = 1;
        a.Ah[0]=H(0); a.Al[0]=L(0); a.Bh[0]=H(5); a.Bl[0]=L(5); a.D[0]=tr;
        a.C[0]=tr + 2 * (size_t)MM_ELEMS; a.Ch[0]=H(6); a.Cl[0]=L(6);
        a.Ah[1]=H(1); a.Al[1]=L(1); a.Bh[1]=H(8); a.Bl[1]=L(8); a.D[1]=tc;
        a.C[1]=tc + 2 * (size_t)MM_ELEMS; a.Ch[1]=H(9); a.Cl[1]=L(9);
        gemm_mma<<<dim3(12, 12, 2), gblk, GEMM_SMEM>>>(a);
    }

    // --- Y_i = Tr_i @ x (B operand = xT slot), i=1..4 (z=4) ---
    {
        const int trs[4] = {0, 4, 5, 6};
        GArgs a = {}; a.mode = 0;
        for (int i = 0; i < 4; i++) {
            a.Ah[i] = H(trs[i]); a.Al[i] = L(trs[i]);
            a.Bh[i] = H(3);      a.Bl[i] = L(3);
            a.D[i]  = nullptr;
            a.C[i]  = y + (size_t)i * MM_ELEMS;
            a.Ch[i] = H(10 + i); a.Cl[i] = L(10 + i);
        }
        gemm_mma<<<dim3(12, 12, 4), gblk, GEMM_SMEM>>>(a);
    }

    // --- Z_{i,j} = Y_i @ Tc_j, ALL 20 in ONE launch (z=20) ---
    {
        const int ysl[5] = {2, 10, 11, 12, 13};      // x, Y1..Y4
        const int tcs[4] = {1, 7, 8, 9};             // Lc, T2c, T3c, T4c
        GArgs a = {}; a.mode = 0;
        for (int j = 1; j <= 4; j++)
            for (int i = 0; i < 5; i++) {
                int b = (j - 1) * 5 + i;
                a.Ah[b] = H(ysl[i]); a.Al[b] = L(ysl[i]);
                a.Bh[b] = H(tcs[j - 1]); a.Bl[b] = L(tcs[j - 1]);
                a.D[b] = nullptr;
                a.C[b] = z + (size_t)(i * 4 + (j - 1)) * MM_ELEMS;
                a.Ch[b] = nullptr; a.Cl[b] = nullptr;
            }
        gemm_mma<<<dim3(12, 12, 20), gblk, GEMM_SMEM>>>(a);
    }

    // --- final contraction (float4) ---
    final_kernel<<<MM_ELEMS / 1024, gblk>>>(x, th, bs, out);
}

// round 14
// speedup vs baseline: 2.7794x; 1.0458x over previous
#include <cuda_runtime.h>
#include <cuda_bf16.h>
#include <cstdint>

#define MDIM 1536
#define MM_ELEMS (1536 * 1536)
#define BM 128
#define BN 128
#define BK 64
#define NSTAGE (MDIM / BK)      // 24
#define TILE_BYTES 16384        // 128 rows x 64 bf16 x 2B
#define STAGE_BYTES (4 * TILE_BYTES)          // 64KB
#define GEMM_SMEM (3 * STAGE_BYTES)           // 196608 (3-stage)

// ---------------- scratch (static __device__, no allocation) ----------------
__device__ float g_TR[3ull * MM_ELEMS];   // T2,T3,T4 of Lr (fp32)
__device__ float g_TC[3ull * MM_ELEMS];   // T2,T3,T4 of Lc (fp32)
__device__ float g_Y [4ull * MM_ELEMS];   // Y1..Y4 (fp32)
__device__ float g_Z [20ull * MM_ELEMS];  // Z (fp32)
// bf16 hi/lo slots: 0:Lr 1:Lc 2:x 3:xT 4..6:TR2..4 7..9:TC2..4 10..13:Y1..4
__device__ __nv_bfloat16 g_bh[14ull * MM_ELEMS];
__device__ __nv_bfloat16 g_bl[14ull * MM_ELEMS];

// ---------------- PTX helpers (plain sm_80+ features only) ----------------
__device__ __forceinline__ uint32_t smem_u32(const void* p) {
    uint32_t a;
    asm("{ .reg .u64 t; cvta.to.shared.u64 t, %1; cvt.u32.u64 %0, t; }" : "=r"(a) : "l"(p));
    return a;
}
__device__ __forceinline__ void cp16(uint32_t dst, const void* src) {
    asm volatile("cp.async.cg.shared.global [%0], [%1], 16;\n" :: "r"(dst), "l"(src));
}
__device__ __forceinline__ void cp_commit() {
    asm volatile("cp.async.commit_group;\n" ::: "memory");
}
template <int N>
__device__ __forceinline__ void cp_wait() {
    asm volatile("cp.async.wait_group %0;\n" :: "n"(N) : "memory");
}
__device__ __forceinline__ void ldsm4(uint32_t* r, uint32_t addr) {
    asm volatile("ldmatrix.sync.aligned.m8n8.x4.shared.b16 {%0,%1,%2,%3}, [%4];"
                 : "=r"(r[0]), "=r"(r[1]), "=r"(r[2]), "=r"(r[3]) : "r"(addr));
}
__device__ __forceinline__ void mma_bf16(float* c, const uint32_t* a, uint32_t b0, uint32_t b1) {
    asm volatile("mma.sync.aligned.m16n8k16.row.col.f32.bf16.bf16.f32 "
                 "{%0,%1,%2,%3}, {%4,%5,%6,%7}, {%8,%9}, {%0,%1,%2,%3};"
                 : "+f"(c[0]), "+f"(c[1]), "+f"(c[2]), "+f"(c[3])
                 : "r"(a[0]), "r"(a[1]), "r"(a[2]), "r"(a[3]), "r"(b0), "r"(b1));
}

// ---------------- batched split-bf16 GEMM (legacy tensor pipe) ----------------
// C = A*B (mode 0)  or  C = 2*A*B - D (mode 1, D==null -> Identity)
// A row-major [m][k]; B as [n][k] (B^T row-major; symmetric B's or explicit xT).
// acc = AhBh + AhBl + AlBh.
#define MAXB 20
struct GArgs {
    const __nv_bfloat16 *Ah[MAXB], *Al[MAXB], *Bh[MAXB], *Bl[MAXB];
    const float* D[MAXB];
    float* C[MAXB];
    __nv_bfloat16 *Ch[MAXB], *Cl[MAXB];
    int mode;
};

__global__ __launch_bounds__(256, 1)
void gemm_mma(GArgs args) {
    extern __shared__ char smem[];
    const int bz = blockIdx.z;
    const __nv_bfloat16* __restrict__ Ah = args.Ah[bz];
    const __nv_bfloat16* __restrict__ Al = args.Al[bz];
    const __nv_bfloat16* __restrict__ Bh = args.Bh[bz];
    const __nv_bfloat16* __restrict__ Bl = args.Bl[bz];
    const float* Dm = args.D[bz];
    float*       C  = args.C[bz];
    __nv_bfloat16* Ch = args.Ch[bz];
    __nv_bfloat16* Cl = args.Cl[bz];

    const uint32_t sb = smem_u32(smem);
    const int tid = threadIdx.x;
    const int wid = tid >> 5;
    const int l   = tid & 31;
    const int wm  = wid & 3;      // 4 warps along M (32 rows each)
    const int wn  = wid >> 2;     // 2 warps along N (64 cols each)
    const int row0 = blockIdx.y * BM;
    const int col0 = blockIdx.x * BN;

    float acc[2][8][4];
#pragma unroll
    for (int mf = 0; mf < 2; mf++)
#pragma unroll
        for (int nf = 0; nf < 8; nf++)
#pragma unroll
            for (int q = 0; q < 4; q++) acc[mf][nf][q] = 0.0f;

    const __nv_bfloat16* P[4] = {Ah, Al, Bh, Bl};
    // per-thread loader constants (same for every stage/tile)
    const int ldr_r   = tid >> 3;          // 0..31 base row step (x4 via +256)
    const int ldr_c16 = tid & 7;           // 16B column within 128B row

    // ---- full-stage loader (prologue only) ----
    auto load_stage = [&](int s, int buf) {
        const int kb = s * BK;
        const uint32_t base = sb + buf * STAGE_BYTES;
#pragma unroll
        for (int t = 0; t < 4; t++) {
            const __nv_bfloat16* p = P[t];
            const int rb = (t < 2) ? row0 : col0;
#pragma unroll
            for (int i = 0; i < 4; i++) {
                int r = ldr_r + 32 * i;
                uint32_t dst = base + t * TILE_BYTES + r * 128 + ((ldr_c16 ^ (r & 7)) << 4);
                cp16(dst, p + (size_t)(rb + r) * MDIM + kb + ldr_c16 * 8);
            }
        }
        cp_commit();
    };

    // ---- compute stage `buf`; interleave issue of prefetch stage ps->pbuf ----
    auto compute = [&](int buf, int ps, int pbuf) {
        const uint32_t base = sb + buf * STAGE_BYTES;
#pragma unroll
        for (int ks = 0; ks < 4; ks++) {
            uint32_t aH[2][4], aL[2][4], bH[4][4], bL[4][4];
            const int c16 = ks * 2 + (l >> 4);
#pragma unroll
            for (int mf = 0; mf < 2; mf++) {
                int ar = wm * 32 + mf * 16 + (l & 15);
                uint32_t off = (uint32_t)(ar * 128 + ((c16 ^ (ar & 7)) << 4));
                ldsm4(aH[mf], base + off);
                ldsm4(aL[mf], base + TILE_BYTES + off);
            }
#pragma unroll
            for (int np = 0; np < 4; np++) {
                int br = wn * 64 + np * 16 + (l & 15);
                uint32_t off = (uint32_t)(br * 128 + ((c16 ^ (br & 7)) << 4));
                ldsm4(bH[np], base + 2 * TILE_BYTES + off);
                ldsm4(bL[np], base + 3 * TILE_BYTES + off);
            }
            // interleaved prefetch: tile t=ks of stage ps (4 cp16 per thread)
            if (ps >= 0) {
                const __nv_bfloat16* p = P[ks];
                const int rb = (ks < 2) ? row0 : col0;
                const int kb = ps * BK;
                const uint32_t pbase = sb + pbuf * STAGE_BYTES + ks * TILE_BYTES;
#pragma unroll
                for (int i = 0; i < 4; i++) {
                    int r = ldr_r + 32 * i;
                    uint32_t dst = pbase + r * 128 + ((ldr_c16 ^ (r & 7)) << 4);
                    cp16(dst, p + (size_t)(rb + r) * MDIM + kb + ldr_c16 * 8);
                }
            }
#pragma unroll
            for (int mf = 0; mf < 2; mf++)
#pragma unroll
                for (int nf = 0; nf < 8; nf++) {
                    const int np = nf >> 1, s2 = nf & 1;
                    mma_bf16(acc[mf][nf], aH[mf], bH[np][s2], bH[np][s2 + 2]);
                    mma_bf16(acc[mf][nf], aH[mf], bL[np][s2], bL[np][s2 + 2]);
                    mma_bf16(acc[mf][nf], aL[mf], bH[np][s2], bH[np][s2 + 2]);
                }
        }
        if (ps >= 0) cp_commit();
    };

    // ---- 3-stage pipeline, ONE wait + ONE barrier per stage ----
    // Iter s: pending groups {g_s, g_{s+1}}; wait<=1 -> g_s done; barrier makes
    // it CTA-visible AND proves compute(s-1) finished everywhere, so prefetch
    // into buf (s+2)%3 == (s-1)%3 during compute(s) is race-free.
    load_stage(0, 0);
    load_stage(1, 1);
    for (int s = 0; s < NSTAGE; s++) {
        if (s + 1 < NSTAGE) cp_wait<1>();
        else                cp_wait<0>();
        __syncthreads();
        const bool pre = (s + 2 < NSTAGE);
        compute(s % 3, pre ? s + 2 : -1, (s + 2) % 3);
    }

    // ---- epilogue ----
    const int mode = args.mode;
#pragma unroll
    for (int mf = 0; mf < 2; mf++) {
#pragma unroll
        for (int nf = 0; nf < 8; nf++) {
            const int r0 = row0 + wm * 32 + mf * 16 + (l >> 2);
            const int r1 = r0 + 8;
            const int cc = col0 + wn * 64 + nf * 8 + (l & 3) * 2;
            float v0 = acc[mf][nf][0], v1 = acc[mf][nf][1];
            float v2 = acc[mf][nf][2], v3 = acc[mf][nf][3];
            if (mode) {
                float d0, d1, d2, d3;
                if (Dm) {
                    d0 = Dm[(size_t)r0 * MDIM + cc];
                    d1 = Dm[(size_t)r0 * MDIM + cc + 1];
                    d2 = Dm[(size_t)r1 * MDIM + cc];
                    d3 = Dm[(size_t)r1 * MDIM + cc + 1];
                } else {
                    d0 = (r0 == cc) ? 1.0f : 0.0f;
                    d1 = (r0 == cc + 1) ? 1.0f : 0.0f;
                    d2 = (r1 == cc) ? 1.0f : 0.0f;
                    d3 = (r1 == cc + 1) ? 1.0f : 0.0f;
                }
                v0 = 2.0f * v0 - d0; v1 = 2.0f * v1 - d1;
                v2 = 2.0f * v2 - d2; v3 = 2.0f * v3 - d3;
            }
            *(float2*)&C[(size_t)r0 * MDIM + cc] = make_float2(v0, v1);
            *(float2*)&C[(size_t)r1 * MDIM + cc] = make_float2(v2, v3);
            if (Ch) {
                __nv_bfloat16 h0 = __float2bfloat16_rn(v0), h1 = __float2bfloat16_rn(v1);
                __nv_bfloat16 h2 = __float2bfloat16_rn(v2), h3 = __float2bfloat16_rn(v3);
                __nv_bfloat162 hp0 = __halves2bfloat162(h0, h1);
                __nv_bfloat162 hp1 = __halves2bfloat162(h2, h3);
                __nv_bfloat162 lp0 = __halves2bfloat162(
                    __float2bfloat16_rn(v0 - __bfloat162float(h0)),
                    __float2bfloat16_rn(v1 - __bfloat162float(h1)));
                __nv_bfloat162 lp1 = __halves2bfloat162(
                    __float2bfloat16_rn(v2 - __bfloat162float(h2)),
                    __float2bfloat16_rn(v3 - __bfloat162float(h3)));
                *(__nv_bfloat162*)&Ch[(size_t)r0 * MDIM + cc] = hp0;
                *(__nv_bfloat162*)&Ch[(size_t)r1 * MDIM + cc] = hp1;
                *(__nv_bfloat162*)&Cl[(size_t)r0 * MDIM + cc] = lp0;
                *(__nv_bfloat162*)&Cl[(size_t)r1 * MDIM + cc] = lp1;
            }
        }
    }
}

// ---------------- fp32 -> bf16 hi/lo converters ----------------
__global__ __launch_bounds__(256)
void conv_kernel(const float* __restrict__ s, __nv_bfloat16* __restrict__ h,
                 __nv_bfloat16* __restrict__ l) {
    int i = blockIdx.x * 256 + threadIdx.x;   // 4 elems per thread
    float4 v = ((const float4*)s)[i];
    float vv[4] = {v.x, v.y, v.z, v.w};
    uint32_t hw[2], lw[2];
#pragma unroll
    for (int q = 0; q < 2; q++) {
        __nv_bfloat16 h0 = __float2bfloat16_rn(vv[2 * q]);
        __nv_bfloat16 h1 = __float2bfloat16_rn(vv[2 * q + 1]);
        __nv_bfloat16 l0 = __float2bfloat16_rn(vv[2 * q]     - __bfloat162float(h0));
        __nv_bfloat16 l1 = __float2bfloat16_rn(vv[2 * q + 1] - __bfloat162float(h1));
        __nv_bfloat162 hp = __halves2bfloat162(h0, h1);
        __nv_bfloat162 lp = __halves2bfloat162(l0, l1);
        hw[q] = *(uint32_t*)&hp;
        lw[q] = *(uint32_t*)&lp;
    }
    ((uint2*)h)[i] = make_uint2(hw[0], hw[1]);
    ((uint2*)l)[i] = make_uint2(lw[0], lw[1]);
}

__global__ __launch_bounds__(256)
void convT_kernel(const float* __restrict__ s, __nv_bfloat16* __restrict__ h,
                  __nv_bfloat16* __restrict__ l) {
    __shared__ float t[32][33];
    const int bx = blockIdx.x * 32, by = blockIdx.y * 32;
    const int x = threadIdx.x, y = threadIdx.y;   // 32 x 8
#pragma unroll
    for (int j = 0; j < 4; j++)
        t[y + 8 * j][x] = s[(size_t)(by + y + 8 * j) * MDIM + bx + x];
    __syncthreads();
#pragma unroll
    for (int j = 0; j < 4; j++) {
        float v = t[x][y + 8 * j];
        __nv_bfloat16 hv = __float2bfloat16_rn(v);
        __nv_bfloat16 lv = __float2bfloat16_rn(v - __bfloat162float(hv));
        size_t o = (size_t)(bx + y + 8 * j) * MDIM + by + x;
        h[o] = hv; l[o] = lv;
    }
}

// ---------------- final contraction (float4 vectorized) ----------------
__global__ __launch_bounds__(256)
void final_kernel(const float* __restrict__ x,
                  const float* __restrict__ theta,
                  const float* __restrict__ bias,
                  float* __restrict__ out) {
    __shared__ float sth[25][32];
    __shared__ float sb[32];
    for (int t = threadIdx.x; t < 800; t += blockDim.x)
        sth[t >> 5][t & 31] = theta[t];
    if (threadIdx.x < 32) sb[threadIdx.x] = bias[threadIdx.x];
    __syncthreads();

    const size_t i4 = (size_t)blockIdx.x * blockDim.x + threadIdx.x;  // float4 index
    float4 z[25];
    z[0] = ((const float4*)x)[i4];
#pragma unroll
    for (int i = 1; i < 5; i++)
        z[i * 5] = ((const float4*)g_Y)[(size_t)(i - 1) * (MM_ELEMS / 4) + i4];
#pragma unroll
    for (int i = 0; i < 5; i++)
#pragma unroll
        for (int j = 1; j < 5; j++)
            z[i * 5 + j] = ((const float4*)g_Z)[(size_t)(i * 4 + j - 1) * (MM_ELEMS / 4) + i4];

#pragma unroll 4
    for (int o = 0; o < 32; o++) {
        float b = sb[o];
        float4 a = make_float4(b, b, b, b);
#pragma unroll
        for (int p = 0; p < 25; p++) {
            float w = sth[p][o];
            a.x = fmaf(z[p].x, w, a.x);
            a.y = fmaf(z[p].y, w, a.y);
            a.z = fmaf(z[p].z, w, a.z);
            a.w = fmaf(z[p].w, w, a.w);
        }
        ((float4*)out)[(size_t)o * (MM_ELEMS / 4) + i4] = a;
    }
}

// ---------------- launch ----------------
extern "C" void kernel_launch(void* const* d_in, const int* in_sizes, int n_in,
                              void* d_out, int out_size) {
    const float* x  = (const float*)d_in[0];
    const float* Lr = (const float*)d_in[1];
    const float* Lc = (const float*)d_in[2];
    const float* th = (const float*)d_in[3];
    const float* bs = (const float*)d_in[4];
    float* out = (float*)d_out;

    cudaFuncSetAttribute(gemm_mma, cudaFuncAttributeMaxDynamicSharedMemorySize, GEMM_SMEM);

    float *tr, *tc, *y, *z;
    __nv_bfloat16 *bh, *bl;
    cudaGetSymbolAddress((void**)&tr, g_TR);
    cudaGetSymbolAddress((void**)&tc, g_TC);
    cudaGetSymbolAddress((void**)&y,  g_Y);
    cudaGetSymbolAddress((void**)&z,  g_Z);
    cudaGetSymbolAddress((void**)&bh, g_bh);
    cudaGetSymbolAddress((void**)&bl, g_bl);

    auto H = [&](int s) { return bh + (size_t)s * MM_ELEMS; };
    auto L = [&](int s) { return bl + (size_t)s * MM_ELEMS; };

    // --- converts: Lr->0, Lc->1, x->2, xT->3 ---
    conv_kernel<<<MM_ELEMS / 1024, 256>>>(Lr, H(0), L(0));
    conv_kernel<<<MM_ELEMS / 1024, 256>>>(Lc, H(1), L(1));
    conv_kernel<<<MM_ELEMS / 1024, 256>>>(x,  H(2), L(2));
    convT_kernel<<<dim3(48, 48), dim3(32, 8)>>>(x, H(3), L(3));

    const dim3 gblk(256);

    // --- Chebyshev recursion, row & col batched (z=2) ---
    {   // T2 = 2*L*L - I  -> slots 4 (row), 7 (col)
        GArgs a = {}; a.mode = 1;
        a.Ah[0]=H(0); a.Al[0]=L(0); a.Bh[0]=H(0); a.Bl[0]=L(0); a.D[0]=nullptr;
        a.C[0]=tr; a.Ch[0]=H(4); a.Cl[0]=L(4);
        a.Ah[1]=H(1); a.Al[1]=L(1); a.Bh[1]=H(1); a.Bl[1]=L(1); a.D[1]=nullptr;
        a.C[1]=tc; a.Ch[1]=H(7); a.Cl[1]=L(7);
        gemm_mma<<<dim3(12, 12, 2), gblk, GEMM_SMEM>>>(a);
    }
    {   // T3 = 2*L*T2 - L  -> slots 5, 8
        GArgs a = {}; a.mode = 1;
        a.Ah[0]=H(0); a.Al[0]=L(0); a.Bh[0]=H(4); a.Bl[0]=L(4); a.D[0]=Lr;
        a.C[0]=tr + MM_ELEMS; a.Ch[0]=H(5); a.Cl[0]=L(5);
        a.Ah[1]=H(1); a.Al[1]=L(1); a.Bh[1]=H(7); a.Bl[1]=L(7); a.D[1]=Lc;
        a.C[1]=tc + MM_ELEMS; a.Ch[1]=H(8); a.Cl[1]=L(8);
        gemm_mma<<<dim3(12, 12, 2), gblk, GEMM_SMEM>>>(a);
    }
    {   // T4 = 2*L*T3 - T2 -> slots 6, 9
        GArgs a = {}; a.mode = 1;
        a.Ah[0]=H(0); a.Al[0]=L(0); a.Bh[0]=H(5); a.Bl[0]=L(5); a.D[0]=tr;
        a.C[0]=tr + 2 * (size_t)MM_ELEMS; a.Ch[0]=H(6); a.Cl[0]=L(6);
        a.Ah[1]=H(1); a.Al[1]=L(1); a.Bh[1]=H(8); a.Bl[1]=L(8); a.D[1]=tc;
        a.C[1]=tc + 2 * (size_t)MM_ELEMS; a.Ch[1]=H(9); a.Cl[1]=L(9);
        gemm_mma<<<dim3(12, 12, 2), gblk, GEMM_SMEM>>>(a);
    }

    // --- Y_i = Tr_i @ x (B operand = xT slot), i=1..4 (z=4) ---
    {
        const int trs[4] = {0, 4, 5, 6};
        GArgs a = {}; a.mode = 0;
        for (int i = 0; i < 4; i++) {
            a.Ah[i] = H(trs[i]); a.Al[i] = L(trs[i]);
            a.Bh[i] = H(3);      a.Bl[i] = L(3);
            a.D[i]  = nullptr;
            a.C[i]  = y + (size_t)i * MM_ELEMS;
            a.Ch[i] = H(10 + i); a.Cl[i] = L(10 + i);
        }
        gemm_mma<<<dim3(12, 12, 4), gblk, GEMM_SMEM>>>(a);
    }

    // --- Z_{i,j} = Y_i @ Tc_j, ALL 20 in ONE launch (z=20) ---
    {
        const int ysl[5] = {2, 10, 11, 12, 13};      // x, Y1..Y4
        const int tcs[4] = {1, 7, 8, 9};             // Lc, T2c, T3c, T4c
        GArgs a = {}; a.mode = 0;
        for (int j = 1; j <= 4; j++)
            for (int i = 0; i < 5; i++) {
                int b = (j - 1) * 5 + i;
                a.Ah[b] = H(ysl[i]); a.Al[b] = L(ysl[i]);
                a.Bh[b] = H(tcs[j - 1]); a.Bl[b] = L(tcs[j - 1]);
                a.D[b] = nullptr;
                a.C[b] = z + (size_t)(i * 4 + (j - 1)) * MM_ELEMS;
                a.Ch[b] = nullptr; a.Cl[b] = nullptr;
            }
        gemm_mma<<<dim3(12, 12, 20), gblk, GEMM_SMEM>>>(a);
    }

    // --- final contraction (float4) ---
    final_kernel<<<MM_ELEMS / 1024, gblk>>>(x, th, bs, out);
}

// round 15
// speedup vs baseline: 2.8959x; 1.0419x over previous
#include <cuda_runtime.h>
#include <cuda_fp16.h>
#include <cstdint>

#define MDIM 1536
#define MM_ELEMS (1536 * 1536)
#define BM 128
#define BN 128
#define BK 64
#define NSTAGE (MDIM / BK)      // 24
#define TILE_BYTES 16384        // 128 rows x 64 fp16 x 2B
#define STAGE_BYTES (4 * TILE_BYTES)          // 64KB
#define GEMM_SMEM (3 * STAGE_BYTES)           // 196608 (3-stage)

// ---------------- scratch (static __device__, no allocation) ----------------
__device__ float g_TR[3ull * MM_ELEMS];   // T2,T3,T4 of Lr (fp32)
__device__ float g_TC[3ull * MM_ELEMS];   // T2,T3,T4 of Lc (fp32)
__device__ float g_Y [4ull * MM_ELEMS];   // Y1..Y4 (fp32)
__device__ float g_Z [20ull * MM_ELEMS];  // Z (fp32)
// fp16 hi/lo slots: 0:Lr 1:Lc 2:x 3:xT 4..6:TR2..4 7..9:TC2..4 10..13:Y1..4
__device__ __half g_bh[14ull * MM_ELEMS];
__device__ __half g_bl[14ull * MM_ELEMS];

// ---------------- PTX helpers (plain sm_80+ features only) ----------------
__device__ __forceinline__ uint32_t smem_u32(const void* p) {
    uint32_t a;
    asm("{ .reg .u64 t; cvta.to.shared.u64 t, %1; cvt.u32.u64 %0, t; }" : "=r"(a) : "l"(p));
    return a;
}
__device__ __forceinline__ void cp16(uint32_t dst, const void* src) {
    asm volatile("cp.async.cg.shared.global [%0], [%1], 16;\n" :: "r"(dst), "l"(src));
}
__device__ __forceinline__ void cp_commit() {
    asm volatile("cp.async.commit_group;\n" ::: "memory");
}
template <int N>
__device__ __forceinline__ void cp_wait() {
    asm volatile("cp.async.wait_group %0;\n" :: "n"(N) : "memory");
}
__device__ __forceinline__ void ldsm4(uint32_t* r, uint32_t addr) {
    asm volatile("ldmatrix.sync.aligned.m8n8.x4.shared.b16 {%0,%1,%2,%3}, [%4];"
                 : "=r"(r[0]), "=r"(r[1]), "=r"(r[2]), "=r"(r[3]) : "r"(addr));
}
__device__ __forceinline__ void mma_f16(float* c, const uint32_t* a, uint32_t b0, uint32_t b1) {
    asm volatile("mma.sync.aligned.m16n8k16.row.col.f32.f16.f16.f32 "
                 "{%0,%1,%2,%3}, {%4,%5,%6,%7}, {%8,%9}, {%0,%1,%2,%3};"
                 : "+f"(c[0]), "+f"(c[1]), "+f"(c[2]), "+f"(c[3])
                 : "r"(a[0]), "r"(a[1]), "r"(a[2]), "r"(a[3]), "r"(b0), "r"(b1));
}

__device__ __forceinline__ void split_h(float v, __half& h, __half& l) {
    h = __float2half_rn(v);
    l = __float2half_rn(v - __half2float(h));
}

// ---------------- batched split-fp16 GEMM (legacy tensor pipe) ----------------
// C = A*B (mode 0)  or  C = 2*A*B - D (mode 1, D==null -> Identity)
// A row-major [m][k]; B as [n][k] (B^T row-major; symmetric B's or explicit xT).
// passes==3: acc = AhBh + AhBl + AlBh   (~fp32-exact: residual AlBl ~ 2^-24)
// passes==2: acc = AhBh + AlBh = A*Bh   (B @ 11 bits: rel err ~ 2^-12; Bl unused)
#define MAXB 20
struct GArgs {
    const __half *Ah[MAXB], *Al[MAXB], *Bh[MAXB], *Bl[MAXB];
    const float* D[MAXB];
    float* C[MAXB];
    __half *Ch[MAXB], *Cl[MAXB];
    int mode;
    int passes;   // 2 or 3
};

__global__ __launch_bounds__(256, 1)
void gemm_mma(GArgs args) {
    extern __shared__ char smem[];
    const int bz = blockIdx.z;
    const __half* __restrict__ Ah = args.Ah[bz];
    const __half* __restrict__ Al = args.Al[bz];
    const __half* __restrict__ Bh = args.Bh[bz];
    const __half* __restrict__ Bl = args.Bl[bz];
    const float* Dm = args.D[bz];
    float*       C  = args.C[bz];
    __half* Ch = args.Ch[bz];
    __half* Cl = args.Cl[bz];
    const bool p3 = (args.passes == 3);

    const uint32_t sb = smem_u32(smem);
    const int tid = threadIdx.x;
    const int wid = tid >> 5;
    const int l   = tid & 31;
    const int wm  = wid & 3;      // 4 warps along M (32 rows each)
    const int wn  = wid >> 2;     // 2 warps along N (64 cols each)
    const int row0 = blockIdx.y * BM;
    const int col0 = blockIdx.x * BN;

    float acc[2][8][4];
#pragma unroll
    for (int mf = 0; mf < 2; mf++)
#pragma unroll
        for (int nf = 0; nf < 8; nf++)
#pragma unroll
            for (int q = 0; q < 4; q++) acc[mf][nf][q] = 0.0f;

    const __half* P[4] = {Ah, Al, Bh, Bl};
    const int ldr_r   = tid >> 3;          // 0..31 base row (+32*i)
    const int ldr_c16 = tid & 7;           // 16B column within 128B row
    const int ntile = p3 ? 4 : 3;          // skip Bl tile when 2-pass

    // ---- full-stage loader (prologue only) ----
    auto load_stage = [&](int s, int buf) {
        const int kb = s * BK;
        const uint32_t base = sb + buf * STAGE_BYTES;
        for (int t = 0; t < ntile; t++) {
            const __half* p = P[t];
            const int rb = (t < 2) ? row0 : col0;
#pragma unroll
            for (int i = 0; i < 4; i++) {
                int r = ldr_r + 32 * i;
                uint32_t dst = base + t * TILE_BYTES + r * 128 + ((ldr_c16 ^ (r & 7)) << 4);
                cp16(dst, p + (size_t)(rb + r) * MDIM + kb + ldr_c16 * 8);
            }
        }
        cp_commit();
    };

    // ---- compute stage `buf`; interleave issue of prefetch stage ps->pbuf ----
    auto compute = [&](int buf, int ps, int pbuf) {
        const uint32_t base = sb + buf * STAGE_BYTES;
#pragma unroll
        for (int ks = 0; ks < 4; ks++) {
            uint32_t aH[2][4], aL[2][4], bH[4][4], bL[4][4];
            const int c16 = ks * 2 + (l >> 4);
#pragma unroll
            for (int mf = 0; mf < 2; mf++) {
                int ar = wm * 32 + mf * 16 + (l & 15);
                uint32_t off = (uint32_t)(ar * 128 + ((c16 ^ (ar & 7)) << 4));
                ldsm4(aH[mf], base + off);
                ldsm4(aL[mf], base + TILE_BYTES + off);
            }
#pragma unroll
            for (int np = 0; np < 4; np++) {
                int br = wn * 64 + np * 16 + (l & 15);
                uint32_t off = (uint32_t)(br * 128 + ((c16 ^ (br & 7)) << 4));
                ldsm4(bH[np], base + 2 * TILE_BYTES + off);
                if (p3) ldsm4(bL[np], base + 3 * TILE_BYTES + off);
            }
            // interleaved prefetch: tile t=ks of stage ps (4 cp16 per thread)
            if (ps >= 0 && ks < ntile) {
                const __half* p = P[ks];
                const int rb = (ks < 2) ? row0 : col0;
                const int kb = ps * BK;
                const uint32_t pbase = sb + pbuf * STAGE_BYTES + ks * TILE_BYTES;
#pragma unroll
                for (int i = 0; i < 4; i++) {
                    int r = ldr_r + 32 * i;
                    uint32_t dst = pbase + r * 128 + ((ldr_c16 ^ (r & 7)) << 4);
                    cp16(dst, p + (size_t)(rb + r) * MDIM + kb + ldr_c16 * 8);
                }
            }
#pragma unroll
            for (int mf = 0; mf < 2; mf++)
#pragma unroll
                for (int nf = 0; nf < 8; nf++) {
                    const int np = nf >> 1, s2 = nf & 1;
                    mma_f16(acc[mf][nf], aH[mf], bH[np][s2], bH[np][s2 + 2]);
                    mma_f16(acc[mf][nf], aL[mf], bH[np][s2], bH[np][s2 + 2]);
                    if (p3) mma_f16(acc[mf][nf], aH[mf], bL[np][s2], bL[np][s2 + 2]);
                }
        }
        if (ps >= 0) cp_commit();
    };

    // ---- 3-stage pipeline, ONE wait + ONE barrier per stage ----
    load_stage(0, 0);
    load_stage(1, 1);
    for (int s = 0; s < NSTAGE; s++) {
        if (s + 1 < NSTAGE) cp_wait<1>();
        else                cp_wait<0>();
        __syncthreads();
        const bool pre = (s + 2 < NSTAGE);
        compute(s % 3, pre ? s + 2 : -1, (s + 2) % 3);
    }

    // ---- epilogue ----
    const int mode = args.mode;
#pragma unroll
    for (int mf = 0; mf < 2; mf++) {
#pragma unroll
        for (int nf = 0; nf < 8; nf++) {
            const int r0 = row0 + wm * 32 + mf * 16 + (l >> 2);
            const int r1 = r0 + 8;
            const int cc = col0 + wn * 64 + nf * 8 + (l & 3) * 2;
            float v0 = acc[mf][nf][0], v1 = acc[mf][nf][1];
            float v2 = acc[mf][nf][2], v3 = acc[mf][nf][3];
            if (mode) {
                float d0, d1, d2, d3;
                if (Dm) {
                    d0 = Dm[(size_t)r0 * MDIM + cc];
                    d1 = Dm[(size_t)r0 * MDIM + cc + 1];
                    d2 = Dm[(size_t)r1 * MDIM + cc];
                    d3 = Dm[(size_t)r1 * MDIM + cc + 1];
                } else {
                    d0 = (r0 == cc) ? 1.0f : 0.0f;
                    d1 = (r0 == cc + 1) ? 1.0f : 0.0f;
                    d2 = (r1 == cc) ? 1.0f : 0.0f;
                    d3 = (r1 == cc + 1) ? 1.0f : 0.0f;
                }
                v0 = 2.0f * v0 - d0; v1 = 2.0f * v1 - d1;
                v2 = 2.0f * v2 - d2; v3 = 2.0f * v3 - d3;
            }
            *(float2*)&C[(size_t)r0 * MDIM + cc] = make_float2(v0, v1);
            *(float2*)&C[(size_t)r1 * MDIM + cc] = make_float2(v2, v3);
            if (Ch) {
                __half h0, h1, h2, h3, l0, l1, l2, l3;
                split_h(v0, h0, l0); split_h(v1, h1, l1);
                split_h(v2, h2, l2); split_h(v3, h3, l3);
                *(__half2*)&Ch[(size_t)r0 * MDIM + cc] = __halves2half2(h0, h1);
                *(__half2*)&Ch[(size_t)r1 * MDIM + cc] = __halves2half2(h2, h3);
                *(__half2*)&Cl[(size_t)r0 * MDIM + cc] = __halves2half2(l0, l1);
                *(__half2*)&Cl[(size_t)r1 * MDIM + cc] = __halves2half2(l2, l3);
            }
        }
    }
}

// ---------------- fp32 -> fp16 hi/lo converters ----------------
__global__ __launch_bounds__(256)
void conv_kernel(const float* __restrict__ s, __half* __restrict__ h,
                 __half* __restrict__ l) {
    int i = blockIdx.x * 256 + threadIdx.x;   // 4 elems per thread
    float4 v = ((const float4*)s)[i];
    float vv[4] = {v.x, v.y, v.z, v.w};
    uint32_t hw[2], lw[2];
#pragma unroll
    for (int q = 0; q < 2; q++) {
        __half h0, h1, l0, l1;
        split_h(vv[2 * q], h0, l0);
        split_h(vv[2 * q + 1], h1, l1);
        __half2 hp = __halves2half2(h0, h1);
        __half2 lp = __halves2half2(l0, l1);
        hw[q] = *(uint32_t*)&hp;
        lw[q] = *(uint32_t*)&lp;
    }
    ((uint2*)h)[i] = make_uint2(hw[0], hw[1]);
    ((uint2*)l)[i] = make_uint2(lw[0], lw[1]);
}

__global__ __launch_bounds__(256)
void convT_kernel(const float* __restrict__ s, __half* __restrict__ h,
                  __half* __restrict__ l) {
    __shared__ float t[32][33];
    const int bx = blockIdx.x * 32, by = blockIdx.y * 32;
    const int x = threadIdx.x, y = threadIdx.y;   // 32 x 8
#pragma unroll
    for (int j = 0; j < 4; j++)
        t[y + 8 * j][x] = s[(size_t)(by + y + 8 * j) * MDIM + bx + x];
    __syncthreads();
#pragma unroll
    for (int j = 0; j < 4; j++) {
        float v = t[x][y + 8 * j];
        __half hv, lv;
        split_h(v, hv, lv);
        size_t o = (size_t)(bx + y + 8 * j) * MDIM + by + x;
        h[o] = hv; l[o] = lv;
    }
}

// ---------------- final contraction (float4 vectorized) ----------------
__global__ __launch_bounds__(256)
void final_kernel(const float* __restrict__ x,
                  const float* __restrict__ theta,
                  const float* __restrict__ bias,
                  float* __restrict__ out) {
    __shared__ float sth[25][32];
    __shared__ float sb[32];
    for (int t = threadIdx.x; t < 800; t += blockDim.x)
        sth[t >> 5][t & 31] = theta[t];
    if (threadIdx.x < 32) sb[threadIdx.x] = bias[threadIdx.x];
    __syncthreads();

    const size_t i4 = (size_t)blockIdx.x * blockDim.x + threadIdx.x;  // float4 index
    float4 z[25];
    z[0] = ((const float4*)x)[i4];
#pragma unroll
    for (int i = 1; i < 5; i++)
        z[i * 5] = ((const float4*)g_Y)[(size_t)(i - 1) * (MM_ELEMS / 4) + i4];
#pragma unroll
    for (int i = 0; i < 5; i++)
#pragma unroll
        for (int j = 1; j < 5; j++)
            z[i * 5 + j] = ((const float4*)g_Z)[(size_t)(i * 4 + j - 1) * (MM_ELEMS / 4) + i4];

#pragma unroll 4
    for (int o = 0; o < 32; o++) {
        float b = sb[o];
        float4 a = make_float4(b, b, b, b);
#pragma unroll
        for (int p = 0; p < 25; p++) {
            float w = sth[p][o];
            a.x = fmaf(z[p].x, w, a.x);
            a.y = fmaf(z[p].y, w, a.y);
            a.z = fmaf(z[p].z, w, a.z);
            a.w = fmaf(z[p].w, w, a.w);
        }
        ((float4*)out)[(size_t)o * (MM_ELEMS / 4) + i4] = a;
    }
}

// ---------------- launch ----------------
extern "C" void kernel_launch(void* const* d_in, const int* in_sizes, int n_in,
                              void* d_out, int out_size) {
    const float* x  = (const float*)d_in[0];
    const float* Lr = (const float*)d_in[1];
    const float* Lc = (const float*)d_in[2];
    const float* th = (const float*)d_in[3];
    const float* bs = (const float*)d_in[4];
    float* out = (float*)d_out;

    cudaFuncSetAttribute(gemm_mma, cudaFuncAttributeMaxDynamicSharedMemorySize, GEMM_SMEM);

    float *tr, *tc, *y, *z;
    __half *bh, *bl;
    cudaGetSymbolAddress((void**)&tr, g_TR);
    cudaGetSymbolAddress((void**)&tc, g_TC);
    cudaGetSymbolAddress((void**)&y,  g_Y);
    cudaGetSymbolAddress((void**)&z,  g_Z);
    cudaGetSymbolAddress((void**)&bh, g_bh);
    cudaGetSymbolAddress((void**)&bl, g_bl);

    auto H = [&](int s) { return bh + (size_t)s * MM_ELEMS; };
    auto L = [&](int s) { return bl + (size_t)s * MM_ELEMS; };

    // --- converts: Lr->0, Lc->1, x->2, xT->3 ---
    conv_kernel<<<MM_ELEMS / 1024, 256>>>(Lr, H(0), L(0));
    conv_kernel<<<MM_ELEMS / 1024, 256>>>(Lc, H(1), L(1));
    conv_kernel<<<MM_ELEMS / 1024, 256>>>(x,  H(2), L(2));
    convT_kernel<<<dim3(48, 48), dim3(32, 8)>>>(x, H(3), L(3));

    const dim3 gblk(256);

    // --- Chebyshev recursion, row & col batched (z=2), 3-pass ---
    {   // T2 = 2*L*L - I  -> slots 4 (row), 7 (col)
        GArgs a = {}; a.mode = 1; a.passes = 3;
        a.Ah[0]=H(0); a.Al[0]=L(0); a.Bh[0]=H(0); a.Bl[0]=L(0); a.D[0]=nullptr;
        a.C[0]=tr; a.Ch[0]=H(4); a.Cl[0]=L(4);
        a.Ah[1]=H(1); a.Al[1]=L(1); a.Bh[1]=H(1); a.Bl[1]=L(1); a.D[1]=nullptr;
        a.C[1]=tc; a.Ch[1]=H(7); a.Cl[1]=L(7);
        gemm_mma<<<dim3(12, 12, 2), gblk, GEMM_SMEM>>>(a);
    }
    {   // T3 = 2*L*T2 - L  -> slots 5, 8
        GArgs a = {}; a.mode = 1; a.passes = 3;
        a.Ah[0]=H(0); a.Al[0]=L(0); a.Bh[0]=H(4); a.Bl[0]=L(4); a.D[0]=Lr;
        a.C[0]=tr + MM_ELEMS; a.Ch[0]=H(5); a.Cl[0]=L(5);
        a.Ah[1]=H(1); a.Al[1]=L(1); a.Bh[1]=H(7); a.Bl[1]=L(7); a.D[1]=Lc;
        a.C[1]=tc + MM_ELEMS; a.Ch[1]=H(8); a.Cl[1]=L(8);
        gemm_mma<<<dim3(12, 12, 2), gblk, GEMM_SMEM>>>(a);
    }
    {   // T4 = 2*L*T3 - T2 -> slots 6, 9
        GArgs a = {}; a.mode = 1; a.passes = 3;
        a.Ah[0]=H(0); a.Al[0]=L(0); a.Bh[0]=H(5); a.Bl[0]=L(5); a.D[0]=tr;
        a.C[0]=tr + 2 * (size_t)MM_ELEMS; a.Ch[0]=H(6); a.Cl[0]=L(6);
        a.Ah[1]=H(1); a.Al[1]=L(1); a.Bh[1]=H(8); a.Bl[1]=L(8); a.D[1]=tc;
        a.C[1]=tc + 2 * (size_t)MM_ELEMS; a.Ch[1]=H(9); a.Cl[1]=L(9);
        gemm_mma<<<dim3(12, 12, 2), gblk, GEMM_SMEM>>>(a);
    }

    // --- Y_i = Tr_i @ x (B operand = xT slot), i=1..4 (z=4), 3-pass ---
    {
        const int trs[4] = {0, 4, 5, 6};
        GArgs a = {}; a.mode = 0; a.passes = 3;
        for (int i = 0; i < 4; i++) {
            a.Ah[i] = H(trs[i]); a.Al[i] = L(trs[i]);
            a.Bh[i] = H(3);      a.Bl[i] = L(3);
            a.D[i]  = nullptr;
            a.C[i]  = y + (size_t)i * MM_ELEMS;
            a.Ch[i] = H(10 + i); a.Cl[i] = L(10 + i);
        }
        gemm_mma<<<dim3(12, 12, 4), gblk, GEMM_SMEM>>>(a);
    }

    // --- Z_{i,j} = Y_i @ Tc_j, ALL 20 in ONE launch (z=20), 2-pass ---
    // Terminal stage: B @ 11 bits -> rel err ~2^-12, no cascade.
    {
        const int ysl[5] = {2, 10, 11, 12, 13};      // x, Y1..Y4
        const int tcs[4] = {1, 7, 8, 9};             // Lc, T2c, T3c, T4c
        GArgs a = {}; a.mode = 0; a.passes = 2;
        for (int j = 1; j <= 4; j++)
            for (int i = 0; i < 5; i++) {
                int b = (j - 1) * 5 + i;
                a.Ah[b] = H(ysl[i]); a.Al[b] = L(ysl[i]);
                a.Bh[b] = H(tcs[j - 1]); a.Bl[b] = L(tcs[j - 1]);
                a.D[b] = nullptr;
                a.C[b] = z + (size_t)(i * 4 + (j - 1)) * MM_ELEMS;
                a.Ch[b] = nullptr; a.Cl[b] = nullptr;
            }
        gemm_mma<<<dim3(12, 12, 20), gblk, GEMM_SMEM>>>(a);
    }

    // --- final contraction (float4) ---
    final_kernel<<<MM_ELEMS / 1024, gblk>>>(x, th, bs, out);
}